// round 2
// baseline (speedup 1.0000x reference)
#include <cuda_runtime.h>
#include <cstdint>

// ---------------- problem constants ----------------
#define NROI   256
#define CCH    1024
#define FH     100
#define FW     50
#define HWPIX  (FH*FW)            // 5000
#define POOLN  7
#define KDIM   (CCH*POOLN*POOLN)  // 50176
#define NHID   1024
#define NCLS   21

// ---------------- GEMM config ----------------
#define SPLITS 32
#define KC     (KDIM/SPLITS)      // 1568
#define BKK    8
#define NIT    (KC/BKK)           // 196
#define BM     128
#define BN     128
#define SMPAD  132                // 128 + 4 pad to kill STS bank conflicts

// ---------------- scratch (allocation-free rule: __device__ globals) ----------------
__device__ float g_fmT[HWPIX*CCH];            // [h*50+w][c]  ~20.5 MB
__device__ float g_P[(size_t)NROI*KDIM];      // pooled features, k = c*49+i*7+j  ~51.4 MB
__device__ float g_part[(size_t)SPLITS*NROI*NHID]; // split-K partials ~33.5 MB
__device__ float g_r[NROI*NHID];              // relu(fc) ~1 MB

// ---------------- packed f32x2 helpers ----------------
__device__ __forceinline__ unsigned long long pack2(float a) {
    unsigned long long r;
    unsigned u = __float_as_uint(a);
    asm("mov.b64 %0, {%1, %1};" : "=l"(r) : "r"(u));
    return r;
}
__device__ __forceinline__ void ffma2(unsigned long long &d, unsigned long long a, unsigned long long b) {
    asm("fma.rn.f32x2 %0, %1, %2, %0;" : "+l"(d) : "l"(a), "l"(b));
}

// ---------------- kernel 1: transpose [C,H,W] -> [HW, C] ----------------
__global__ void transpose_kernel(const float* __restrict__ fm) {
    __shared__ float tile[32][33];
    int p0 = blockIdx.x * 32;         // position (h*50+w)
    int c0 = blockIdx.y * 32;         // channel
    int x = threadIdx.x, y0 = threadIdx.y;   // block (32, 8)
#pragma unroll
    for (int r = 0; r < 4; r++) {
        int c = c0 + y0 + r * 8;
        int p = p0 + x;
        tile[y0 + r * 8][x] = (p < HWPIX) ? fm[(size_t)c * HWPIX + p] : 0.f;
    }
    __syncthreads();
#pragma unroll
    for (int r = 0; r < 4; r++) {
        int p = p0 + y0 + r * 8;
        int c = c0 + x;
        if (p < HWPIX) g_fmT[(size_t)p * CCH + c] = tile[x][y0 + r * 8];
    }
}

// ---------------- kernel 2: ROI adaptive max-pool ----------------
// thread = one channel of one ROI. Loads coalesce across c (fmT is c-contiguous).
// Note reference unpack: roi=[x1,y1,x2,y2] read as h0,w0,h1,w1 (x maps to H axis).
__global__ __launch_bounds__(256) void pool_kernel(const int* __restrict__ props) {
    int r = blockIdx.x;
    int c = blockIdx.y * 256 + threadIdx.x;

    int x1 = props[4 * r + 0]; if (x1 < 0) x1 = 0;
    int y1 = props[4 * r + 1]; if (y1 < 0) y1 = 0;
    int x2 = props[4 * r + 2]; if (x2 < 0) x2 = 0;
    int y2 = props[4 * r + 3]; if (y2 < 0) y2 = 0;
    int h0 = x1 >> 4, w0 = y1 >> 4, h1 = x2 >> 4, w1 = y2 >> 4;
    int sh = h1 - h0 + 1;
    int sw = w1 - w0 + 1;

    float* out = g_P + (size_t)r * KDIM + (size_t)c * (POOLN * POOLN);
    const float* __restrict__ fT = g_fmT;

    for (int i = 0; i < POOLN; i++) {
        int hs = h0 + (i * sh) / POOLN;
        int he = h0 + ((i + 1) * sh + POOLN - 1) / POOLN;   // ceil
        for (int j = 0; j < POOLN; j++) {
            int ws = w0 + (j * sw) / POOLN;
            int we = w0 + ((j + 1) * sw + POOLN - 1) / POOLN;
            float m = -3.402823466e+38f;
            for (int h = hs; h < he; h++) {
                const float* row = fT + ((size_t)(h * FW) + ws) * CCH + c;
                for (int w = ws; w < we; w++) {
                    m = fmaxf(m, *row);
                    row += CCH;
                }
            }
            out[i * POOLN + j] = m;
        }
    }
}

// ---------------- kernel 3: split-K SGEMM with packed f32x2 FMA ----------------
// C_part[z] = P[mtile, kchunk] @ W[ntile, kchunk]^T     (both K-contiguous "NT")
__global__ __launch_bounds__(256) void gemm_kernel(const float* __restrict__ Wt) {
    __shared__ __align__(16) float As[2][BKK][SMPAD];
    __shared__ __align__(16) float Bs[2][BKK][SMPAD];

    int tid   = threadIdx.x;
    int mbase = blockIdx.y * BM;
    int nbase = blockIdx.x * BN;
    int z     = blockIdx.z;
    size_t kbase = (size_t)z * KC;

    int lrow = tid >> 1;            // 0..127
    int lcol = (tid & 1) * 4;       // 0 or 4
    const float* aptr = g_P + (size_t)(mbase + lrow) * KDIM + kbase + lcol;
    const float* bptr = Wt  + (size_t)(nbase + lrow) * KDIM + kbase + lcol;

    int tx = tid & 15, ty = tid >> 4;

    unsigned long long acc[8][4];
#pragma unroll
    for (int i = 0; i < 8; i++)
#pragma unroll
        for (int j = 0; j < 4; j++) acc[i][j] = 0ull;

    // prologue: tile 0 -> buf 0
    float4 av = *(const float4*)aptr;
    float4 bv = *(const float4*)bptr;
    As[0][lcol + 0][lrow] = av.x; As[0][lcol + 1][lrow] = av.y;
    As[0][lcol + 2][lrow] = av.z; As[0][lcol + 3][lrow] = av.w;
    Bs[0][lcol + 0][lrow] = bv.x; Bs[0][lcol + 1][lrow] = bv.y;
    Bs[0][lcol + 2][lrow] = bv.z; Bs[0][lcol + 3][lrow] = bv.w;
    __syncthreads();
    av = *(const float4*)(aptr + BKK);
    bv = *(const float4*)(bptr + BKK);

    for (int t = 0; t < NIT; t++) {
        int cbuf = t & 1;
        if (t + 1 < NIT) {
            int nb = cbuf ^ 1;
            As[nb][lcol + 0][lrow] = av.x; As[nb][lcol + 1][lrow] = av.y;
            As[nb][lcol + 2][lrow] = av.z; As[nb][lcol + 3][lrow] = av.w;
            Bs[nb][lcol + 0][lrow] = bv.x; Bs[nb][lcol + 1][lrow] = bv.y;
            Bs[nb][lcol + 2][lrow] = bv.z; Bs[nb][lcol + 3][lrow] = bv.w;
        }
        if (t + 2 < NIT) {
            av = *(const float4*)(aptr + (size_t)(t + 2) * BKK);
            bv = *(const float4*)(bptr + (size_t)(t + 2) * BKK);
        }
#pragma unroll
        for (int k = 0; k < BKK; k++) {
            float4 A0 = *(const float4*)&As[cbuf][k][ty * 8];
            float4 A1 = *(const float4*)&As[cbuf][k][ty * 8 + 4];
            ulonglong2 B0 = *(const ulonglong2*)&Bs[cbuf][k][tx * 8];
            ulonglong2 B1 = *(const ulonglong2*)&Bs[cbuf][k][tx * 8 + 4];
            unsigned long long b0 = B0.x, b1 = B0.y, b2 = B1.x, b3 = B1.y;
            float a_[8] = {A0.x, A0.y, A0.z, A0.w, A1.x, A1.y, A1.z, A1.w};
#pragma unroll
            for (int i = 0; i < 8; i++) {
                unsigned long long a2 = pack2(a_[i]);
                ffma2(acc[i][0], a2, b0);
                ffma2(acc[i][1], a2, b1);
                ffma2(acc[i][2], a2, b2);
                ffma2(acc[i][3], a2, b3);
            }
        }
        __syncthreads();
    }

    // epilogue: write partials (8-byte packed stores, even n -> aligned)
#pragma unroll
    for (int i = 0; i < 8; i++) {
        size_t idx = (size_t)z * NROI * NHID
                   + (size_t)(mbase + ty * 8 + i) * NHID + nbase + tx * 8;
        unsigned long long* pp = (unsigned long long*)(g_part + idx);
        pp[0] = acc[i][0]; pp[1] = acc[i][1]; pp[2] = acc[i][2]; pp[3] = acc[i][3];
    }
}

// ---------------- kernel 4: fixed-order split reduction + bias + relu ----------------
__global__ __launch_bounds__(256) void reduce_kernel(const float* __restrict__ fc_b) {
    int idx = blockIdx.x * 256 + threadIdx.x;      // < 256*1024
    int n = idx & (NHID - 1);
    float s = fc_b[n];
#pragma unroll
    for (int zz = 0; zz < SPLITS; zz++)
        s += g_part[(size_t)zz * NROI * NHID + idx];
    g_r[idx] = fmaxf(s, 0.f);
}

// ---------------- kernel 5: cls head, argmax, reg gather ----------------
__global__ __launch_bounds__(128) void head_kernel(
    const float* __restrict__ cls_w, const float* __restrict__ cls_b,
    const float* __restrict__ reg_w, const float* __restrict__ reg_b,
    float* __restrict__ out)
{
    __shared__ float rv[NHID];
    __shared__ float clsv[NCLS];
    __shared__ int bestI;
    int r = blockIdx.x, tid = threadIdx.x;
    const float* rr = g_r + (size_t)r * NHID;
    for (int i = tid * 4; i < NHID; i += 128 * 4)
        *(float4*)&rv[i] = *(const float4*)&rr[i];
    __syncthreads();

    int warp = tid >> 5, lane = tid & 31;
    for (int n = warp; n < NCLS; n += 4) {
        const float* wrow = cls_w + (size_t)n * NHID;
        float s = 0.f;
        for (int k = lane; k < NHID; k += 32) s = fmaf(wrow[k], rv[k], s);
#pragma unroll
        for (int o = 16; o; o >>= 1) s += __shfl_xor_sync(0xffffffffu, s, o);
        if (lane == 0) {
            float v = s + cls_b[n];
            clsv[n] = v;
            out[(size_t)r * NCLS + n] = v;       // cls_out [256,21]
        }
    }
    __syncthreads();
    if (tid == 0) {
        int b = 0; float bvv = clsv[0];
        for (int n = 1; n < NCLS; n++)
            if (clsv[n] > bvv) { bvv = clsv[n]; b = n; }   // first-max, matches argmax
        bestI = b;
    }
    __syncthreads();
    {
        int q = warp;   // 4 warps -> 4 reg outputs
        int rowi = bestI * 4 + q;
        const float* wrow = reg_w + (size_t)rowi * NHID;
        float s = 0.f;
        for (int k = lane; k < NHID; k += 32) s = fmaf(wrow[k], rv[k], s);
#pragma unroll
        for (int o = 16; o; o >>= 1) s += __shfl_xor_sync(0xffffffffu, s, o);
        if (lane == 0)
            out[(size_t)NROI * NCLS + (size_t)r * 4 + q] = s + reg_b[rowi];  // reg_out [256,4]
    }
}

// ---------------- launch ----------------
extern "C" void kernel_launch(void* const* d_in, const int* in_sizes, int n_in,
                              void* d_out, int out_size) {
    const float* fm    = (const float*)d_in[0];
    const int*   props = (const int*)  d_in[1];
    const float* fc_w  = (const float*)d_in[2];
    const float* fc_b  = (const float*)d_in[3];
    const float* cls_w = (const float*)d_in[4];
    const float* cls_b = (const float*)d_in[5];
    const float* reg_w = (const float*)d_in[6];
    const float* reg_b = (const float*)d_in[7];
    float* out = (float*)d_out;

    transpose_kernel<<<dim3((HWPIX + 31) / 32, CCH / 32), dim3(32, 8)>>>(fm);
    pool_kernel<<<dim3(NROI, CCH / 256), 256>>>(props);
    gemm_kernel<<<dim3(BN == 128 ? NHID / BN : 8, NROI / BM, SPLITS), 256>>>(fc_w);
    reduce_kernel<<<(NROI * NHID) / 256, 256>>>(fc_b);
    head_kernel<<<NROI, 128>>>(cls_w, cls_b, reg_w, reg_b, out);
}

// round 6
// speedup vs baseline: 1.8172x; 1.8172x over previous
#include <cuda_runtime.h>
#include <cuda_bf16.h>
#include <cstdint>

// ---------------- problem constants ----------------
#define NROI   256
#define CCH    1024
#define FH     100
#define FW     50
#define HWPIX  (FH*FW)            // 5000
#define POOLN  7
#define KDIM   (CCH*POOLN*POOLN)  // 50176
#define NHID   1024
#define NCLS   21

// ---------------- GEMM config ----------------
#define SPLITS 49
#define KC     (KDIM/SPLITS)      // 1024
#define KB     16                 // fp32 K elements per stage (one k16 mma step)
#define NSTG   (KC/KB)            // 64
#define BM     128
#define BN     128
// bf16 elems per smem row: 16 data + 8 pad = 48 BYTES -> every ldmatrix row
// address is 16B-aligned (REQUIRED), and the 8 rows of each 8x8 matrix map to
// distinct 16B segments mod 128B -> conflict-free LDSM.
#define LDS_ROW 24

// ---------------- scratch (allocation-free rule: __device__ globals) ----------------
__device__ float g_fmT[HWPIX*CCH];                    // ~20.5 MB
__device__ float g_P[(size_t)NROI*KDIM];              // ~51.4 MB
__device__ float g_part[(size_t)SPLITS*NROI*NHID];    // ~51.4 MB
__device__ float g_r[NROI*NHID];                      // 1 MB

// ---------------- helpers ----------------
__device__ __forceinline__ uint32_t smem_u32(const void* p) {
    uint32_t a;
    asm("{ .reg .u64 t; cvta.to.shared.u64 t, %1; cvt.u32.u64 %0, t; }" : "=r"(a) : "l"(p));
    return a;
}

__device__ __forceinline__ void ldsm4(uint32_t* r, uint32_t addr) {
    asm volatile("ldmatrix.sync.aligned.m8n8.x4.shared.b16 {%0,%1,%2,%3}, [%4];"
        : "=r"(r[0]), "=r"(r[1]), "=r"(r[2]), "=r"(r[3]) : "r"(addr));
}

__device__ __forceinline__ void hmma(float* c, const uint32_t* a, const uint32_t* b) {
    asm volatile("mma.sync.aligned.m16n8k16.row.col.f32.bf16.bf16.f32 "
        "{%0,%1,%2,%3}, {%4,%5,%6,%7}, {%8,%9}, {%0,%1,%2,%3};"
        : "+f"(c[0]), "+f"(c[1]), "+f"(c[2]), "+f"(c[3])
        : "r"(a[0]), "r"(a[1]), "r"(a[2]), "r"(a[3]), "r"(b[0]), "r"(b[1]));
}

// fp32 -> (bf16 hi by truncation [exact], bf16 lo rn) for 4 elems; 8B store per plane
__device__ __forceinline__ void cvt_store(float4 v, uint8_t* hi_p, uint8_t* lo_p, uint32_t off) {
    uint32_t u0 = __float_as_uint(v.x), u1 = __float_as_uint(v.y);
    uint32_t u2 = __float_as_uint(v.z), u3 = __float_as_uint(v.w);
    uint32_t h01, h23;
    asm("prmt.b32 %0, %1, %2, 0x7632;" : "=r"(h01) : "r"(u0), "r"(u1));
    asm("prmt.b32 %0, %1, %2, 0x7632;" : "=r"(h23) : "r"(u2), "r"(u3));
    float l0 = v.x - __uint_as_float(u0 & 0xffff0000u);
    float l1 = v.y - __uint_as_float(u1 & 0xffff0000u);
    float l2 = v.z - __uint_as_float(u2 & 0xffff0000u);
    float l3 = v.w - __uint_as_float(u3 & 0xffff0000u);
    uint32_t q01, q23;
    asm("cvt.rn.satfinite.bf16x2.f32 %0, %1, %2;" : "=r"(q01) : "f"(l1), "f"(l0));
    asm("cvt.rn.satfinite.bf16x2.f32 %0, %1, %2;" : "=r"(q23) : "f"(l3), "f"(l2));
    *(uint2*)(hi_p + off) = make_uint2(h01, h23);
    *(uint2*)(lo_p + off) = make_uint2(q01, q23);
}

// ---------------- kernel 1: transpose [C,H,W] -> [HW, C] ----------------
__global__ void transpose_kernel(const float* __restrict__ fm) {
    __shared__ float tile[32][33];
    int p0 = blockIdx.x * 32, c0 = blockIdx.y * 32;
    int x = threadIdx.x, y0 = threadIdx.y;
#pragma unroll
    for (int r = 0; r < 4; r++) {
        int c = c0 + y0 + r * 8, p = p0 + x;
        tile[y0 + r * 8][x] = (p < HWPIX) ? fm[(size_t)c * HWPIX + p] : 0.f;
    }
    __syncthreads();
#pragma unroll
    for (int r = 0; r < 4; r++) {
        int p = p0 + y0 + r * 8, c = c0 + x;
        if (p < HWPIX) g_fmT[(size_t)p * CCH + c] = tile[x][y0 + r * 8];
    }
}

// ---------------- kernel 2: ROI adaptive max-pool ----------------
__global__ __launch_bounds__(256) void pool_kernel(const int* __restrict__ props) {
    int r = blockIdx.x;
    int c = blockIdx.y * 256 + threadIdx.x;
    int x1 = props[4 * r + 0]; if (x1 < 0) x1 = 0;
    int y1 = props[4 * r + 1]; if (y1 < 0) y1 = 0;
    int x2 = props[4 * r + 2]; if (x2 < 0) x2 = 0;
    int y2 = props[4 * r + 3]; if (y2 < 0) y2 = 0;
    int h0 = x1 >> 4, w0 = y1 >> 4, h1 = x2 >> 4, w1 = y2 >> 4;
    int sh = h1 - h0 + 1, sw = w1 - w0 + 1;
    float* out = g_P + (size_t)r * KDIM + (size_t)c * (POOLN * POOLN);
    const float* __restrict__ fT = g_fmT;
    for (int i = 0; i < POOLN; i++) {
        int hs = h0 + (i * sh) / POOLN;
        int he = h0 + ((i + 1) * sh + POOLN - 1) / POOLN;
        for (int j = 0; j < POOLN; j++) {
            int ws = w0 + (j * sw) / POOLN;
            int we = w0 + ((j + 1) * sw + POOLN - 1) / POOLN;
            float m = -3.402823466e+38f;
            for (int h = hs; h < he; h++) {
                const float* row = fT + ((size_t)(h * FW) + ws) * CCH + c;
                for (int w = ws; w < we; w++) { m = fmaxf(m, *row); row += CCH; }
            }
            out[i * POOLN + j] = m;
        }
    }
}

// ---------------- kernel 3: mma.sync bf16 hi/lo split GEMM (split-K 49) ----------------
// partial[z] = P[128 rows, KC] @ W[128 rows, KC]^T, fp32 acc,
// 3 products per k16: AhiWhi + AhiWlo + AloWhi
__global__ __launch_bounds__(256, 1) void gemm_kernel(const float* __restrict__ Wt) {
    // [buf][plane(hi,lo)][128 rows * LDS_ROW]   (2 arrays x 24 KB = 48 KB static)
    __shared__ __align__(16) __nv_bfloat16 smA[2][2][128 * LDS_ROW];
    __shared__ __align__(16) __nv_bfloat16 smW[2][2][128 * LDS_ROW];

    int tid = threadIdx.x, lane = tid & 31, wid = tid >> 5;
    int wm = wid >> 1;            // 0..3 : M warp coord (32 rows each)
    int wn = wid & 1;             // 0..1 : N warp coord (64 cols each)
    int nbase = blockIdx.x * BN;
    int mbase = blockIdx.y * BM;
    int z = blockIdx.z;
    size_t kbase = (size_t)z * KC;

    const float* Ab = g_P + (size_t)mbase * KDIM + kbase;
    const float* Wb = Wt  + (size_t)nbase * KDIM + kbase;

    int r0 = tid >> 2;            // 0..63
    int c4 = tid & 3;             // float4 slot within k16
    uint32_t off0 = (uint32_t)(r0 * LDS_ROW + c4 * 4) * 2;          // bytes
    uint32_t off1 = (uint32_t)((r0 + 64) * LDS_ROW + c4 * 4) * 2;

    float acc[2][8][4] = {};

    // prologue: stage 0 into regs
    float4 la0 = *(const float4*)(Ab + (size_t)r0 * KDIM + c4 * 4);
    float4 la1 = *(const float4*)(Ab + (size_t)(r0 + 64) * KDIM + c4 * 4);
    float4 lw0 = *(const float4*)(Wb + (size_t)r0 * KDIM + c4 * 4);
    float4 lw1 = *(const float4*)(Wb + (size_t)(r0 + 64) * KDIM + c4 * 4);

    // per-warp fragment smem byte offsets (within a plane); all 16B-aligned
    uint32_t aoff = (uint32_t)(((wm * 32 + (lane & 15)) * LDS_ROW + ((lane >> 4) & 1) * 8) * 2);
    uint32_t aoff16 = (uint32_t)(16 * LDS_ROW * 2);   // +16 rows
    uint32_t boff = (uint32_t)(((wn * 64 + (lane & 7) + ((lane >> 4) & 1) * 8) * LDS_ROW
                               + ((lane >> 3) & 1) * 8) * 2);
    uint32_t boff16 = (uint32_t)(16 * LDS_ROW * 2);

    for (int t = 0; t < NSTG; t++) {
        int b = t & 1;
        cvt_store(la0, (uint8_t*)smA[b][0], (uint8_t*)smA[b][1], off0);
        cvt_store(la1, (uint8_t*)smA[b][0], (uint8_t*)smA[b][1], off1);
        cvt_store(lw0, (uint8_t*)smW[b][0], (uint8_t*)smW[b][1], off0);
        cvt_store(lw1, (uint8_t*)smW[b][0], (uint8_t*)smW[b][1], off1);
        if (t + 1 < NSTG) {
            int kt = (t + 1) * KB;
            la0 = *(const float4*)(Ab + (size_t)r0 * KDIM + kt + c4 * 4);
            la1 = *(const float4*)(Ab + (size_t)(r0 + 64) * KDIM + kt + c4 * 4);
            lw0 = *(const float4*)(Wb + (size_t)r0 * KDIM + kt + c4 * 4);
            lw1 = *(const float4*)(Wb + (size_t)(r0 + 64) * KDIM + kt + c4 * 4);
        }
        __syncthreads();

        uint32_t af[2][2][4];                 // [plane][mi][4]
        uint32_t bf_[2][8][2];                // [plane][ni][2]
#pragma unroll
        for (int p = 0; p < 2; p++) {
            uint32_t baseA = smem_u32(smA[b][p]);
            ldsm4(af[p][0], baseA + aoff);
            ldsm4(af[p][1], baseA + aoff + aoff16);
            uint32_t baseW = smem_u32(smW[b][p]);
#pragma unroll
            for (int nf = 0; nf < 4; nf++) {
                uint32_t r[4];
                ldsm4(r, baseW + boff + nf * boff16);
                bf_[p][nf * 2][0] = r[0]; bf_[p][nf * 2][1] = r[1];
                bf_[p][nf * 2 + 1][0] = r[2]; bf_[p][nf * 2 + 1][1] = r[3];
            }
        }
#pragma unroll
        for (int mi = 0; mi < 2; mi++)
#pragma unroll
            for (int ni = 0; ni < 8; ni++) {
                hmma(acc[mi][ni], af[0][mi], bf_[0][ni]);   // hi*hi
                hmma(acc[mi][ni], af[0][mi], bf_[1][ni]);   // hi*lo
                hmma(acc[mi][ni], af[1][mi], bf_[0][ni]);   // lo*hi
            }
    }

    // epilogue: write split-K partials
#pragma unroll
    for (int mi = 0; mi < 2; mi++) {
        int row = mbase + wm * 32 + mi * 16 + (lane >> 2);
#pragma unroll
        for (int ni = 0; ni < 8; ni++) {
            int col = nbase + wn * 64 + ni * 8 + (lane & 3) * 2;
            size_t base = ((size_t)z * NROI + row) * NHID + col;
            *(float2*)(g_part + base)            = make_float2(acc[mi][ni][0], acc[mi][ni][1]);
            *(float2*)(g_part + base + 8 * NHID) = make_float2(acc[mi][ni][2], acc[mi][ni][3]);
        }
    }
}

// ---------------- kernel 4: fixed-order split reduction + bias + relu ----------------
__global__ __launch_bounds__(256) void reduce_kernel(const float* __restrict__ fc_b) {
    int idx = blockIdx.x * 256 + threadIdx.x;
    int n = idx & (NHID - 1);
    float s = fc_b[n];
#pragma unroll 7
    for (int zz = 0; zz < SPLITS; zz++)
        s += g_part[(size_t)zz * NROI * NHID + idx];
    g_r[idx] = fmaxf(s, 0.f);
}

// ---------------- kernel 5: cls head, argmax, reg gather ----------------
__global__ __launch_bounds__(128) void head_kernel(
    const float* __restrict__ cls_w, const float* __restrict__ cls_b,
    const float* __restrict__ reg_w, const float* __restrict__ reg_b,
    float* __restrict__ out)
{
    __shared__ float rv[NHID];
    __shared__ float clsv[NCLS];
    __shared__ int bestI;
    int r = blockIdx.x, tid = threadIdx.x;
    const float* rr = g_r + (size_t)r * NHID;
    for (int i = tid * 4; i < NHID; i += 128 * 4)
        *(float4*)&rv[i] = *(const float4*)&rr[i];
    __syncthreads();

    int warp = tid >> 5, lane = tid & 31;
    for (int n = warp; n < NCLS; n += 4) {
        const float* wrow = cls_w + (size_t)n * NHID;
        float s = 0.f;
        for (int k = lane; k < NHID; k += 32) s = fmaf(wrow[k], rv[k], s);
#pragma unroll
        for (int o = 16; o; o >>= 1) s += __shfl_xor_sync(0xffffffffu, s, o);
        if (lane == 0) {
            float v = s + cls_b[n];
            clsv[n] = v;
            out[(size_t)r * NCLS + n] = v;
        }
    }
    __syncthreads();
    if (tid == 0) {
        int b = 0; float bvv = clsv[0];
        for (int n = 1; n < NCLS; n++)
            if (clsv[n] > bvv) { bvv = clsv[n]; b = n; }
        bestI = b;
    }
    __syncthreads();
    {
        int rowi = bestI * 4 + warp;
        const float* wrow = reg_w + (size_t)rowi * NHID;
        float s = 0.f;
        for (int k = lane; k < NHID; k += 32) s = fmaf(wrow[k], rv[k], s);
#pragma unroll
        for (int o = 16; o; o >>= 1) s += __shfl_xor_sync(0xffffffffu, s, o);
        if (lane == 0)
            out[(size_t)NROI * NCLS + (size_t)r * 4 + warp] = s + reg_b[rowi];
    }
}

// ---------------- launch ----------------
extern "C" void kernel_launch(void* const* d_in, const int* in_sizes, int n_in,
                              void* d_out, int out_size) {
    const float* fm    = (const float*)d_in[0];
    const int*   props = (const int*)  d_in[1];
    const float* fc_w  = (const float*)d_in[2];
    const float* fc_b  = (const float*)d_in[3];
    const float* cls_w = (const float*)d_in[4];
    const float* cls_b = (const float*)d_in[5];
    const float* reg_w = (const float*)d_in[6];
    const float* reg_b = (const float*)d_in[7];
    float* out = (float*)d_out;

    transpose_kernel<<<dim3((HWPIX + 31) / 32, CCH / 32), dim3(32, 8)>>>(fm);
    pool_kernel<<<dim3(NROI, CCH / 256), 256>>>(props);
    gemm_kernel<<<dim3(NHID / BN, NROI / BM, SPLITS), 256>>>(fc_w);
    reduce_kernel<<<(NROI * NHID) / 256, 256>>>(fc_b);
    head_kernel<<<NROI, 128>>>(cls_w, cls_b, reg_w, reg_b, out);
}